// round 7
// baseline (speedup 1.0000x reference)
#include <cuda_runtime.h>
#include <math.h>

#define HH 1024
#define WW 1024
#define PLANES 24           // 8 batch * 3 channels
#define RAD 25
#define TAPS 51

// 100 MB scratch for the horizontal-pass result (no cudaMalloc allowed)
__device__ float g_tmp[(size_t)PLANES * HH * WW];

// ---------------- compile-time gaussian weights --------------------------
struct WTab { float w[TAPS]; };

__host__ __device__ constexpr double cexp_series(double x) {
    double term = 1.0, sum = 1.0;
    for (int i = 1; i < 40; ++i) { term *= x / (double)i; sum += term; }
    return sum;
}

__host__ __device__ constexpr WTab make_wtab() {
    WTab t{};
    double g[TAPS] = {};
    double s = 0.0;
    for (int i = 0; i < TAPS; ++i) {
        double d = (double)(i - RAD);
        g[i] = cexp_series(-d * d / (2.0 * 15.0 * 15.0));
        s += g[i];
    }
    for (int i = 0; i < TAPS; ++i) t.w[i] = (float)(g[i] / s);
    return t;
}

__constant__ WTab c_wt = make_wtab();

// ---------------- packed f32x2 helpers -----------------------------------
__device__ __forceinline__ unsigned long long pk2(float a, float b) {
    unsigned long long r;
    asm("mov.b64 %0, {%1, %2};" : "=l"(r) : "f"(a), "f"(b));
    return r;
}
__device__ __forceinline__ void upk2(unsigned long long v, float& a, float& b) {
    asm("mov.b64 {%0, %1}, %2;" : "=f"(a), "=f"(b) : "l"(v));
}
__device__ __forceinline__ unsigned long long ffma2(unsigned long long a,
                                                    unsigned long long b,
                                                    unsigned long long c) {
    unsigned long long d;
    asm("fma.rn.f32x2 %0, %1, %2, %3;" : "=l"(d) : "l"(a), "l"(b), "l"(c));
    return d;
}

// ---------------- pass 1: horizontal 51-tap conv (packed) ----------------
// One block = one image row. 128 threads, 8 outputs/thread = 4 packed pairs.
// Skewed scalar smem: addr(i) = i + i/32 -> conflict-free for lane-stride-8.
#define SKW(i) ((i) + ((i) >> 5))

__global__ void __launch_bounds__(128) hpass(const float* __restrict__ x) {
    const int row = blockIdx.x;                       // 0 .. PLANES*HH-1
    const float* src = x + (size_t)row * WW;
    float* dst = g_tmp + (size_t)row * WW;

    __shared__ float s[SKW(WW + 2 * RAD - 1) + 2];    // skewed, ~1108 floats
    __shared__ unsigned long long wb[TAPS];           // broadcast weight pairs {w,w}

    const int tid = threadIdx.x;
    if (tid < TAPS) wb[tid] = pk2(c_wt.w[tid], c_wt.w[tid]);

    for (int i = tid; i < WW + 2 * RAD; i += 128) {
        int j = i - RAD;
        s[SKW(i)] = (j >= 0 && j < WW) ? src[j] : 0.0f;
    }
    __syncthreads();

    const int b = tid * 8;

    unsigned long long a0 = 0ull, a1 = 0ull, a2 = 0ull, a3 = 0ull;
    float d0 = s[SKW(b)];
    #pragma unroll
    for (int k = 0; k <= 56; ++k) {
        float d1 = s[SKW(b + k + 1)];
        unsigned long long P = pk2(d0, d1);           // {s[b+k], s[b+k+1]}
        if (k <= 50)           a0 = ffma2(P, wb[k],     a0);
        if (k >= 2 && k <= 52) a1 = ffma2(P, wb[k - 2], a1);
        if (k >= 4 && k <= 54) a2 = ffma2(P, wb[k - 4], a2);
        if (k >= 6)            a3 = ffma2(P, wb[k - 6], a3);
        d0 = d1;
    }

    float o0, o1, o2, o3, o4, o5, o6, o7;
    upk2(a0, o0, o1); upk2(a1, o2, o3);
    upk2(a2, o4, o5); upk2(a3, o6, o7);
    reinterpret_cast<float4*>(dst + b)[0] = make_float4(o0, o1, o2, o3);
    reinterpret_cast<float4*>(dst + b)[1] = make_float4(o4, o5, o6, o7);
}

// ---------------- pass 2: vertical 51-tap conv + blend (packed) ----------
// Block: 128 cols x 32 rows. 128 threads: pair p = tid%64 (2 cols), half h = tid/64
// (16 rows). smem tile 82 x 128 floats = 42 KB. Rolling 16-entry packed window.
#define TYV 32
#define SRV (TYV + 2 * RAD)     // 82

__global__ void __launch_bounds__(128) vpass(const float* __restrict__ x,
                                             const float* __restrict__ amt_p,
                                             float* __restrict__ out) {
    __shared__ float s[SRV][128];
    __shared__ unsigned long long wb[TAPS];

    const int tid = threadIdx.x;
    if (tid < TAPS) wb[tid] = pk2(c_wt.w[tid], c_wt.w[tid]);

    const int plane = blockIdx.z;
    const int x0 = blockIdx.x * 128;
    const int y0 = blockIdx.y * TYV;
    const float* tp = g_tmp + (size_t)plane * HH * WW;

    // Cooperative float4 fill of the 82x128 tile (2624 float4s / 128 threads)
    for (int i = tid; i < SRV * 32; i += 128) {
        int r = i >> 5, c4 = (i & 31) << 2;
        int gy = y0 - RAD + r;
        float4 v = make_float4(0.f, 0.f, 0.f, 0.f);
        if ((unsigned)gy < HH)
            v = *reinterpret_cast<const float4*>(tp + (size_t)gy * WW + x0 + c4);
        *reinterpret_cast<float4*>(&s[r][c4]) = v;
    }
    __syncthreads();

    const int p = tid & 63;          // column pair (cols 2p, 2p+1)
    const int h = tid >> 6;          // row half
    const int rbase = h * 16;

    unsigned long long v[16];
    #pragma unroll
    for (int j = 0; j < 15; ++j)
        v[j] = *reinterpret_cast<const unsigned long long*>(&s[rbase + j][2 * p]);

    unsigned long long acc[16];
    #pragma unroll
    for (int i = 0; i < 16; ++i) acc[i] = 0ull;

    #pragma unroll
    for (int d = 0; d <= 50; ++d) {
        v[(d + 15) & 15] =
            *reinterpret_cast<const unsigned long long*>(&s[rbase + d + 15][2 * p]);
        unsigned long long wd = wb[d];
        #pragma unroll
        for (int ii = 0; ii < 16; ++ii)
            acc[ii] = ffma2(v[(d + ii) & 15], wd, acc[ii]);
    }

    // amount = sigmoid(param) * 0.4 ; result = clip(x + blur*1.2*amount*(1-x))
    const float amount = 0.4f / (1.0f + expf(-amt_p[0]));
    const float kk = 1.2f * amount;

    const float* xp = x + (size_t)plane * HH * WW;
    float* op = out + (size_t)plane * HH * WW;

    #pragma unroll
    for (int ii = 0; ii < 16; ++ii) {
        const int gy = y0 + rbase + ii;
        const size_t off = (size_t)gy * WW + x0 + 2 * p;
        float2 xv = *reinterpret_cast<const float2*>(xp + off);
        float b0, b1;
        upk2(acc[ii], b0, b1);
        float r0 = xv.x + b0 * kk * (1.0f - xv.x);
        float r1 = xv.y + b1 * kk * (1.0f - xv.y);
        r0 = fminf(fmaxf(r0, 0.0f), 1.0f);
        r1 = fminf(fmaxf(r1, 0.0f), 1.0f);
        *reinterpret_cast<float2*>(op + off) = make_float2(r0, r1);
    }
}

extern "C" void kernel_launch(void* const* d_in, const int* in_sizes, int n_in,
                              void* d_out, int out_size) {
    const float* x   = (const float*)d_in[0];
    const float* amt = (const float*)d_in[1];
    float* out = (float*)d_out;

    hpass<<<PLANES * HH, 128>>>(x);
    dim3 grid(WW / 128, HH / TYV, PLANES);
    vpass<<<grid, 128>>>(x, amt, out);
}